// round 16
// baseline (speedup 1.0000x reference)
#include <cuda_runtime.h>
#include <cstdint>

#define IN_DIM 512
#define HID    512
#define OUT_DIM 256
#define TSTEPS 16
#define M_MAX  32768
#define HL_PITCH 576   // hlist row pitch in u32 entries -> 2304 B, mult of 16
#define OF_PITCH 32    // offs row pitch (u16) -> 64 B aligned rows
#define M_CHUNK 16384  // pipeline chunk (2 chunks)

// Scratch (device globals - allocation-free rule)
// g_hlist entries are PRE-SCALED byte offsets into W2Ts: h * 256 (= h * W2T_PITCH * 4)
__device__ float          g_pre1[(size_t)M_MAX * HID];
__device__ __align__(16) unsigned int   g_hlist[(size_t)M_MAX * HL_PITCH];
__device__ __align__(16) unsigned short g_offs[(size_t)M_MAX * OF_PITCH];

__device__ __forceinline__ void dup2(unsigned long long& d, float s)
{
    asm("mov.b64 %0, {%1, %1};" : "=l"(d) : "f"(s));
}
__device__ __forceinline__ void fma2(unsigned long long& acc,
                                     unsigned long long a, unsigned long long b)
{
    asm("fma.rn.f32x2 %0, %1, %2, %0;" : "+l"(acc) : "l"(a), "l"(b));
}
__device__ __forceinline__ void addx2(unsigned long long& a, unsigned long long w)
{
    asm("add.rn.f32x2 %0, %0, %1;" : "+l"(a) : "l"(w));
}

// ---------------------------------------------------------------------------
// Kernel 1: pre1 = x @ W1^T + b1. (unchanged; + m0 chunk offset)
// ---------------------------------------------------------------------------
#define KC 8
#define SPA 132
#define SPB 260
__global__ void __launch_bounds__(256, 1) gemm1_kernel(
    const float* __restrict__ A,
    const float* __restrict__ W1,
    const float* __restrict__ b1,
    int m0)
{
    __shared__ float As[2][KC][SPA];
    __shared__ float Bs[2][KC][SPB];

    const int tid  = threadIdx.x;
    const int lane = tid & 31;
    const int warp = tid >> 5;
    const int bm   = m0 + blockIdx.x * 128;
    const int bn   = blockIdx.y * 256;

    const int lm = lane >> 3;
    const int ln = lane & 7;
    const int row0 = (warp & 3) * 32 + lm * 8;
    const int nhalf = (warp >> 2) * 128;

    const int arow = tid >> 1;
    const int ak4  = (tid & 1) * 4;

    const float* Ag  = A  + (size_t)(bm + arow)       * IN_DIM + ak4;
    const float* Bg0 = W1 + (size_t)(bn + arow)       * IN_DIM + ak4;
    const float* Bg1 = W1 + (size_t)(bn + arow + 128) * IN_DIM + ak4;

    unsigned long long accp[8][8];
#pragma unroll
    for (int i = 0; i < 8; i++)
#pragma unroll
        for (int j = 0; j < 8; j++) accp[i][j] = 0ull;

    float4 pa, pb0, pb1;

    pa  = *(const float4*)(Ag);
    pb0 = *(const float4*)(Bg0);
    pb1 = *(const float4*)(Bg1);
    {
        As[0][ak4+0][arow] = pa.x;  As[0][ak4+1][arow] = pa.y;
        As[0][ak4+2][arow] = pa.z;  As[0][ak4+3][arow] = pa.w;
        Bs[0][ak4+0][arow] = pb0.x; Bs[0][ak4+1][arow] = pb0.y;
        Bs[0][ak4+2][arow] = pb0.z; Bs[0][ak4+3][arow] = pb0.w;
        Bs[0][ak4+0][arow+128] = pb1.x; Bs[0][ak4+1][arow+128] = pb1.y;
        Bs[0][ak4+2][arow+128] = pb1.z; Bs[0][ak4+3][arow+128] = pb1.w;
    }
    __syncthreads();

    int cur = 0;
    for (int k0 = 0; k0 < IN_DIM; k0 += KC) {
        const int nk = k0 + KC;
        if (nk < IN_DIM) {
            pa  = *(const float4*)(Ag  + nk);
            pb0 = *(const float4*)(Bg0 + nk);
            pb1 = *(const float4*)(Bg1 + nk);
        }
#pragma unroll
        for (int kk = 0; kk < KC; kk++) {
            float4 a0 = *(const float4*)&As[cur][kk][row0];
            float4 a1 = *(const float4*)&As[cur][kk][row0 + 4];
            unsigned long long bq[8];
#pragma unroll
            for (int q = 0; q < 4; q++) {
                ulonglong2 bl = *(const ulonglong2*)&Bs[cur][kk][nhalf + q * 32 + ln * 4];
                bq[2*q]   = bl.x;
                bq[2*q+1] = bl.y;
            }
            unsigned long long av2[8];
            dup2(av2[0], a0.x); dup2(av2[1], a0.y);
            dup2(av2[2], a0.z); dup2(av2[3], a0.w);
            dup2(av2[4], a1.x); dup2(av2[5], a1.y);
            dup2(av2[6], a1.z); dup2(av2[7], a1.w);
#pragma unroll
            for (int i = 0; i < 8; i++)
#pragma unroll
                for (int j = 0; j < 8; j++)
                    fma2(accp[i][j], av2[i], bq[j]);
        }
        if (nk < IN_DIM) {
            const int nxt = cur ^ 1;
            As[nxt][ak4+0][arow] = pa.x;  As[nxt][ak4+1][arow] = pa.y;
            As[nxt][ak4+2][arow] = pa.z;  As[nxt][ak4+3][arow] = pa.w;
            Bs[nxt][ak4+0][arow] = pb0.x; Bs[nxt][ak4+1][arow] = pb0.y;
            Bs[nxt][ak4+2][arow] = pb0.z; Bs[nxt][ak4+3][arow] = pb0.w;
            Bs[nxt][ak4+0][arow+128] = pb1.x; Bs[nxt][ak4+1][arow+128] = pb1.y;
            Bs[nxt][ak4+2][arow+128] = pb1.z; Bs[nxt][ak4+3][arow+128] = pb1.w;
            __syncthreads();
            cur = nxt;
        }
    }

#pragma unroll
    for (int q = 0; q < 4; q++) {
        const int colq = nhalf + q * 32 + ln * 4;
        const float4 bb = *(const float4*)&b1[bn + colq];
#pragma unroll
        for (int i = 0; i < 8; i++) {
            union { unsigned long long u; float2 f; } c0, c1;
            c0.u = accp[i][2*q];
            c1.u = accp[i][2*q+1];
            float4 o = make_float4(c0.f.x + bb.x, c0.f.y + bb.y,
                                   c1.f.x + bb.z, c1.f.y + bb.w);
            *(float4*)(g_pre1 + (size_t)(bm + row0 + i) * HID + bn + colq) = o;
        }
    }
}

// ---------------------------------------------------------------------------
// Kernel 2: 4 rows/block counting sort. Entries written as PRE-SCALED byte
// offsets h<<8 (pad = 512<<8 -> zero row). Buckets padded to multiples of 4.
// ---------------------------------------------------------------------------
#define BK_ROWS 4
__global__ void __launch_bounds__(512) bucketize_kernel(int m0)
{
    const int h    = threadIdx.x;
    const int lane = h & 31;
    const int warp = h >> 5;
    const int row_base = m0 + blockIdx.x * BK_ROWS;

    float p[BK_ROWS];
#pragma unroll
    for (int r = 0; r < BK_ROWS; r++)
        p[r] = g_pre1[(size_t)(row_base + r) * HID + h];

    __shared__ int wcnt[16][17];
    __shared__ int wpre[16][17];
    __shared__ int tot[17];
    __shared__ int base[18];

#pragma unroll
    for (int r = 0; r < BK_ROWS; r++) {
        const int row = row_base + r;

        int k = 0;
        float m = 0.f;
#pragma unroll
        for (int t = 1; t <= TSTEPS; t++) {
            m += p[r];
            if (m > 0.5f) { k = t; break; }
        }

        __syncthreads();
        if (threadIdx.x < 16 * 17) ((int*)wcnt)[threadIdx.x] = 0;
        __syncthreads();

        unsigned peers = __match_any_sync(0xffffffffu, k);
        int rank = __popc(peers & ((1u << lane) - 1u));
        if (rank == 0) wcnt[warp][k] = __popc(peers);
        __syncthreads();

        if (threadIdx.x < 17) {
            int b = threadIdx.x;
            int s = 0;
#pragma unroll
            for (int w = 0; w < 16; w++) { wpre[w][b] = s; s += wcnt[w][b]; }
            tot[b] = s;
        }
        __syncthreads();

        if (warp == 0) {
            int sz = 0;
            if (lane < 16) sz = (tot[lane + 1] + 3) & ~3;
            int s = sz;
#pragma unroll
            for (int d = 1; d < 16; d <<= 1) {
                int t = __shfl_up_sync(0xffffffffu, s, d);
                if (lane >= d) s += t;
            }
            if (lane < 16) base[lane + 1] = s - sz;
            if (lane == 15) base[17] = s;
        }
        __syncthreads();

        unsigned int* hrow = g_hlist + (size_t)row * HL_PITCH;
        if (k > 0) {
            int pos = base[k] + wpre[warp][k] + rank;
            hrow[pos] = ((unsigned int)h) << 8;   // pre-scaled byte offset
        }
        if (threadIdx.x < 16) {
            int b = threadIdx.x + 1;
            int sz = tot[b];
            int pad = (sz + 3) & ~3;
            for (int q = sz; q < pad; q++) hrow[base[b] + q] = 512u << 8;
        }
        if (threadIdx.x < 16)
            g_offs[(size_t)row * OF_PITCH + threadIdx.x + 1] =
                (unsigned short)base[threadIdx.x + 2];
        if (threadIdx.x == 16)
            g_offs[(size_t)row * OF_PITCH] = 0;
    }
}

// ---------------------------------------------------------------------------
// Kernel 3: 1024 threads, warps fully independent after W2Ts staging.
// Index stream = pre-scaled byte offsets; one LDG.128 per 4 entries
// (rolling uint4 prefetch, pitch-bounded), gather = IADD + LDS.64 only.
// ---------------------------------------------------------------------------
#define W2T_PITCH 64
#define W2T_ROWS  513
#define W2T_BYTES (W2T_ROWS * W2T_PITCH * 4)   // 131328
#define TT_BYTES  (16 * 32 * 33 * 4)           // 67584
#define ROWS_PER_BLOCK 128
#define P2_SMEM_BYTES (W2T_BYTES + TT_BYTES)   // 198912

__global__ void __launch_bounds__(1024, 1) phase2_kernel(
    const float* __restrict__ W2,
    const float* __restrict__ b2,
    float* __restrict__ out,
    int m0)
{
    extern __shared__ char smem_raw[];
    float* W2Ts = (float*)smem_raw;                 // [513][64]
    float* TT   = (float*)(smem_raw + W2T_BYTES);   // transpose staging only

    const int tid    = threadIdx.x;
    const int w      = tid >> 5;
    const int lane   = tid & 31;
    const int o2     = lane * 2;
    const int o_base = blockIdx.y * 64;

    if (w < 16) {
        float* tile = TT + w * 32 * 33;
#pragma unroll
        for (int tt = 0; tt < 2; tt++) {
            const int t   = w + tt * 16;
            const int oo0 = (t & 1) * 32;
            const int hh0 = (t >> 1) * 32;
#pragma unroll
            for (int r = 0; r < 32; r++) {
                tile[r * 33 + lane] =
                    W2[(size_t)(o_base + oo0 + r) * HID + hh0 + lane];
            }
            __syncwarp();
#pragma unroll
            for (int r2 = 0; r2 < 32; r2++) {
                W2Ts[(hh0 + r2) * W2T_PITCH + oo0 + lane] = tile[lane * 33 + r2];
            }
            __syncwarp();
        }
    }
    if (tid < 64) W2Ts[512 * W2T_PITCH + tid] = 0.f;
    __syncthreads();

    const float2 bb = *(const float2*)&b2[o_base + o2];
    const char* W2o = (const char*)(W2Ts + o2);   // byte base for offset adds
    const int row0 = m0 + blockIdx.x * ROWS_PER_BLOCK;

#pragma unroll
    for (int rr = 0; rr < ROWS_PER_BLOCK / 32; rr++) {
        const int row = row0 + rr * 32 + w;
        const unsigned int* ml = g_hlist + (size_t)row * HL_PITCH;

        const uint4 oa = *(const uint4*)(g_offs + (size_t)row * OF_PITCH);
        const uint4 ob = *(const uint4*)(g_offs + (size_t)row * OF_PITCH + 8);
        const unsigned int oc = *(const unsigned int*)(g_offs + (size_t)row * OF_PITCH + 16);
        const unsigned int ow[9] = {oa.x, oa.y, oa.z, oa.w, ob.x, ob.y, ob.z, ob.w, oc};

        float2 Ck[16];
        int idx = 0;
        uint4 pk = *(const uint4*)ml;   // prefetch first 4 offsets
#pragma unroll
        for (int k = 1; k <= TSTEPS; k++) {
            const int e = (int)((ow[k >> 1] >> ((k & 1) * 16)) & 0xFFFFu);
            unsigned long long accA = 0ull, accB = 0ull;
            for (; idx < e; idx += 4) {
                const uint4 cur = pk;
                pk = *(const uint4*)&ml[idx + 4];   // pitch-bounded prefetch
                unsigned long long w0 = *(const unsigned long long*)(W2o + cur.x);
                unsigned long long w1 = *(const unsigned long long*)(W2o + cur.y);
                unsigned long long w2 = *(const unsigned long long*)(W2o + cur.z);
                unsigned long long w3 = *(const unsigned long long*)(W2o + cur.w);
                addx2(accA, w0);
                addx2(accB, w1);
                addx2(accA, w2);
                addx2(accB, w3);
            }
            addx2(accA, accB);
            union { unsigned long long u; float2 f; } cvt;
            cvt.u = accA;
            Ck[k - 1] = cvt.f;
        }

        float m2x = 0.f, m2y = 0.f, scx = 0.f, scy = 0.f;
#pragma unroll
        for (int t = 1; t <= TSTEPS; t++) {
            float yx = 0.f, yy = 0.f;
#pragma unroll
            for (int d = 1; d <= TSTEPS; d++)
                if (t % d == 0) { yx += Ck[d - 1].x; yy += Ck[d - 1].y; }
            m2x = (m2x + yx) + bb.x;
            m2y = (m2y + yy) + bb.y;
            if (m2x > 0.5f) { scx += 1.f; m2x = 0.f; }
            if (m2y > 0.5f) { scy += 1.f; m2y = 0.f; }
        }
        float2 res = make_float2(scx * 0.0625f, scy * 0.0625f);
        *(float2*)&out[(size_t)row * OUT_DIM + o_base + o2] = res;
    }
}

// ---------------------------------------------------------------------------
// Launch: 2-chunk pipeline, fork/join via events.
// ---------------------------------------------------------------------------
extern "C" void kernel_launch(void* const* d_in, const int* in_sizes, int n_in,
                              void* d_out, int out_size)
{
    const float* x  = (const float*)d_in[0];
    const float* W1 = (const float*)d_in[1];
    const float* b1 = (const float*)d_in[2];
    const float* W2 = (const float*)d_in[3];
    const float* b2 = (const float*)d_in[4];
    float* out = (float*)d_out;

    static cudaStream_t s2 = nullptr;
    static cudaEvent_t evG0 = nullptr, evP0 = nullptr;
    if (s2 == nullptr) {
        cudaStreamCreateWithFlags(&s2, cudaStreamNonBlocking);
        cudaEventCreateWithFlags(&evG0, cudaEventDisableTiming);
        cudaEventCreateWithFlags(&evP0, cudaEventDisableTiming);
    }

    cudaFuncSetAttribute(phase2_kernel,
                         cudaFuncAttributeMaxDynamicSharedMemorySize,
                         P2_SMEM_BYTES);

    dim3 g1(M_CHUNK / 128, HID / 256);
    dim3 g2(M_CHUNK / ROWS_PER_BLOCK, OUT_DIM / 64);
    const int bkg = M_CHUNK / BK_ROWS;

    gemm1_kernel<<<g1, 256>>>(x, W1, b1, 0);
    cudaEventRecord(evG0, 0);

    gemm1_kernel<<<g1, 256>>>(x, W1, b1, M_CHUNK);

    cudaStreamWaitEvent(s2, evG0, 0);
    bucketize_kernel<<<bkg, 512, 0, s2>>>(0);
    phase2_kernel<<<g2, 1024, P2_SMEM_BYTES, s2>>>(W2, b2, out, 0);
    cudaEventRecord(evP0, s2);

    bucketize_kernel<<<bkg, 512>>>(M_CHUNK);
    phase2_kernel<<<g2, 1024, P2_SMEM_BYTES>>>(W2, b2, out, M_CHUNK);

    cudaStreamWaitEvent(0, evP0, 0);
}